// round 15
// baseline (speedup 1.0000x reference)
#include <cuda_runtime.h>
#include <cuda_bf16.h>
#include <math.h>

// Problem constants (fixed by setup_inputs): B=32, N=M=1024, F=4
#define BB    32
#define NN    1024
#define MM    1024
#define BT    256             // block threads (8 warps -> 2 per SMSP)
#define RR    4               // rows per thread (256*4 = 1024)
#define CC    4               // columns per step
#define NG    (MM / CC)       // 256 column groups
#define NWARP (BT / 32)       // 8

// Epoch-skew parameters: barrier every KS steps; warp boundary gap = KS.
#define KS      8
#define WSKEW   (32 + KS - 1)                 // 39: sigma = lane + 39*warp
#define SIGMAX  (31 + WSKEW * (NWARP - 1))    // 304
#define STEPS   (NG + SIGMAX)                 // 560 (multiple of 8; last cell at s=559)
#define EPOCHS  (STEPS / KS)                  // 70

__device__ float g_loss[BB];
__device__ int   g_done;     // zero-init; self-resetting each launch

__device__ __forceinline__ float fsqrt_approx(float x) {
    float r;
    asm("sqrt.approx.f32 %0, %1;" : "=f"(r) : "f"(x));
    return r;
}

__global__ __launch_bounds__(BT, 1)
void dtw_fused(const float* __restrict__ preds, const float* __restrict__ targs,
               const float* __restrict__ subcoef, float* __restrict__ out)
{
    const int b    = blockIdx.x;
    const int tid  = threadIdx.x;
    const int lane = tid & 31;
    const int warp = tid >> 5;
    const int sig  = lane + WSKEW * warp;     // thread skew
    const int wlo  = WSKEW * warp;            // warp-uniform active window
    const int whi  = wlo + 31 + NG;           // [wlo, whi)

    __shared__ float2 txy[MM];                // 8 KB target basis
    __shared__ float4 sbD[2][KS][NWARP];      // handoff D: {bot0..bot3}
    __shared__ float4 sbA[2][KS][NWARP];      // handoff A: {Ab0..Ab3}

    const float* pb = preds + (size_t)b * NN * 4;
    const float* tb = targs + (size_t)b * MM * 4;
    const float INF = __int_as_float(0x7f800000);
    const float c0s = subcoef[0];
    const float c1s = subcoef[1];

    // ---- init ----
    for (int idx = tid; idx < MM; idx += BT)
        txy[idx] = *(const float2*)(tb + (size_t)idx * 4);
    for (int idx = tid; idx < 2 * KS * NWARP; idx += BT) {
        ((float4*)sbD)[idx] = make_float4(INF, INF, INF, INF);
        ((float4*)sbA)[idx] = make_float4(0.0f, 0.0f, 0.0f, 0.0f);
    }

    float px[RR], py[RR], left[RR], Aleft[RR];
    #pragma unroll
    for (int q = 0; q < RR; ++q) {
        const float2 pv = *(const float2*)(pb + (size_t)(tid * RR + q) * 4);
        px[q] = pv.x; py[q] = pv.y;
        left[q]  = INF;
        Aleft[q] = 0.0f;
    }
    __syncthreads();

    // =====================================================================
    // Forward DP with loss propagation, 4 columns per step: thread owns rows
    // 4t..4t+3; at step s it processes column group g = s - sigma (columns
    // 4g..4g+3), carrying
    //   D[i,j] = cost(i,j) + min(D[i-1,j-1], D[i-1,j], D[i,j-1])
    //   A[i,j] = A[argmin parent] + |dx|*c0 + |dy|*c1
    // Parent select: first-min equality order [diag, up, left] = jnp.argmin.
    // In-warp handoff: 8 shfls (neighbor bottoms at the 4 columns); the diag
    // operand at column 4g-1 is CACHED from the previous step's nb3/na3
    // (identity holds across the KS-gap smem slots too). Warp boundary: two
    // float4 slots, double-buffered per epoch, one barrier per KS steps.
    // Cost/loss terms computed inline (16 cells of ILP hide the MUFUs).
    // Answer = A at (NN-1, MM-1), held by thread BT-1 after step STEPS-1.
    // =====================================================================
    float bot0 = INF, bot1 = INF, bot2 = INF, bot3 = INF;
    float Ab0 = 0.0f, Ab1 = 0.0f, Ab2 = 0.0f, Ab3 = 0.0f;
    float cnb3 = INF, cna3 = 0.0f;            // cached diag operands (col 4g-1)

    for (int e = 0; e < EPOCHS; ++e) {
        const int par = e & 1;
        #pragma unroll
        for (int ks = 0; ks < KS; ++ks) {
            const int s = e * KS + ks;

            // ---- handoff ----
            float nb0 = __shfl_up_sync(0xffffffffu, bot0, 1);
            float nb1 = __shfl_up_sync(0xffffffffu, bot1, 1);
            float nb2 = __shfl_up_sync(0xffffffffu, bot2, 1);
            float nb3 = __shfl_up_sync(0xffffffffu, bot3, 1);
            float na0 = __shfl_up_sync(0xffffffffu, Ab0, 1);
            float na1 = __shfl_up_sync(0xffffffffu, Ab1, 1);
            float na2 = __shfl_up_sync(0xffffffffu, Ab2, 1);
            float na3 = __shfl_up_sync(0xffffffffu, Ab3, 1);
            if (lane == 0) {
                if (warp == 0) {
                    nb0 = INF; nb1 = INF; nb2 = INF; nb3 = INF;
                    na0 = 0.0f; na1 = 0.0f; na2 = 0.0f; na3 = 0.0f;
                } else {
                    const float4 vD = sbD[par ^ 1][ks][warp - 1];  // producer step s-KS
                    nb0 = vD.x; nb1 = vD.y; nb2 = vD.z; nb3 = vD.w;
                    const float4 vA = sbA[par ^ 1][ks][warp - 1];
                    na0 = vA.x; na1 = vA.y; na2 = vA.z; na3 = vA.w;
                }
            }

            // ---- DP body (warp-uniformly skipped outside active window) ----
            if (s >= wlo && s < whi) {
                const int g = s - sig;
                if ((unsigned)g < (unsigned)NG) {
                    const int c = g * CC;
                    float curP[RR], AcurP[RR];

                    // ---- column c+0 (diag from cache) ----
                    {
                        const float2 t0 = txy[c];
                        float up = nb0, dg = cnb3, Aup = na0, Adg = cna3;
                        #pragma unroll
                        for (int q = 0; q < RR; ++q) {
                            const float lf  = left[q];
                            const float Alf = Aleft[q];
                            const float pm  = fminf(dg, lf);
                            float best = fminf(up, pm);
                            const bool p0 = (best == dg);
                            const bool p1 = (best == up);
                            const float Asel = p0 ? Adg : (p1 ? Aup : Alf);
                            if (q == 0) best = (best == INF) ? 0.0f : best;  // (0,0) seed
                            const float dx = px[q] - t0.x;
                            const float dy = py[q] - t0.y;
                            const float cst = fsqrt_approx(fmaf(dx, dx, dy * dy));
                            const float lcv = fmaf(fabsf(dy), c1s, fabsf(dx) * c0s);
                            const float cur  = best + cst;
                            const float Acur = Asel + lcv;
                            dg = lf;  Adg = Alf;
                            up = cur; Aup = Acur;
                            curP[q] = cur; AcurP[q] = Acur;
                        }
                        bot0 = curP[RR - 1]; Ab0 = AcurP[RR - 1];
                    }

                    // ---- columns c+1..c+3 ----
                    #pragma unroll
                    for (int k = 1; k < CC; ++k) {
                        const float2 tk = txy[c + k];
                        float up, dg, Aup, Adg;
                        if (k == 1) { up = nb1; dg = nb0; Aup = na1; Adg = na0; }
                        else if (k == 2) { up = nb2; dg = nb1; Aup = na2; Adg = na1; }
                        else { up = nb3; dg = nb2; Aup = na3; Adg = na2; }
                        #pragma unroll
                        for (int q = 0; q < RR; ++q) {
                            const float lf  = curP[q];
                            const float Alf = AcurP[q];
                            const float pm  = fminf(dg, lf);
                            const float best = fminf(up, pm);
                            const bool p0 = (best == dg);
                            const bool p1 = (best == up);
                            const float Asel = p0 ? Adg : (p1 ? Aup : Alf);
                            const float dx = px[q] - tk.x;
                            const float dy = py[q] - tk.y;
                            const float cst = fsqrt_approx(fmaf(dx, dx, dy * dy));
                            const float lcv = fmaf(fabsf(dy), c1s, fabsf(dx) * c0s);
                            const float cur  = best + cst;
                            const float Acur = Asel + lcv;
                            dg = lf;  Adg = Alf;
                            up = cur; Aup = Acur;
                            curP[q] = cur; AcurP[q] = Acur;
                        }
                        if (k == 1) { bot1 = curP[RR - 1]; Ab1 = AcurP[RR - 1]; }
                        else if (k == 2) { bot2 = curP[RR - 1]; Ab2 = AcurP[RR - 1]; }
                        else { bot3 = curP[RR - 1]; Ab3 = AcurP[RR - 1]; }
                    }

                    #pragma unroll
                    for (int q = 0; q < RR; ++q) {
                        left[q] = curP[q]; Aleft[q] = AcurP[q];
                    }
                }
            }

            if (lane == 31) {
                sbD[par][ks][warp] = make_float4(bot0, bot1, bot2, bot3);
                sbA[par][ks][warp] = make_float4(Ab0, Ab1, Ab2, Ab3);
            }

            // update diag cache AFTER use (every step, guard-independent)
            cnb3 = nb3; cna3 = na3;
        }
        __syncthreads();
    }

    // ---- result: thread BT-1's Ab3 is A at (NN-1, MM-1) ----
    if (tid == BT - 1) {
        g_loss[b] = Ab3;
        __threadfence();
        const int old = atomicAdd(&g_done, 1);
        if (old == BB - 1) {
            __threadfence();
            float t2 = 0.0f;
            #pragma unroll
            for (int x = 0; x < BB; ++x) t2 += g_loss[x];
            out[0] = t2;
            g_done = 0;   // self-reset for next graph replay
        }
    }
}

extern "C" void kernel_launch(void* const* d_in, const int* in_sizes, int n_in,
                              void* d_out, int out_size)
{
    const float* preds   = (const float*)d_in[0];
    const float* targs   = (const float*)d_in[1];
    const float* subcoef = (const float*)d_in[2];
    float* out = (float*)d_out;

    dtw_fused<<<BB, BT>>>(preds, targs, subcoef, out);
}

// round 16
// speedup vs baseline: 1.0076x; 1.0076x over previous
#include <cuda_runtime.h>
#include <cuda_bf16.h>
#include <math.h>

// Problem constants (fixed by setup_inputs): B=32, N=M=1024, F=4
#define BB    32
#define NN    1024
#define MM    1024
#define BT    256             // block threads (8 warps -> 2 per SMSP)
#define RR    4               // rows per thread (256*4 = 1024)
#define NG    (MM / 2)        // 512 column groups (2 cols per group)
#define NWARP (BT / 32)       // 8

// Epoch-skew parameters: barrier every KS steps; warp boundary gap = KS.
#define KS      8
#define WSKEW   (32 + KS - 1)                 // 39: sigma = lane + 39*warp
#define SIGMAX  (31 + WSKEW * (NWARP - 1))    // 304
#define STEPS   (NG + SIGMAX)                 // 816 (multiple of 8; last cell at s=815)
#define EPOCHS  (STEPS / KS)                  // 102

__device__ float g_loss[BB];
__device__ int   g_done;     // zero-init; self-resetting each launch

__device__ __forceinline__ float fsqrt_approx(float x) {
    float r;
    asm("sqrt.approx.f32 %0, %1;" : "=f"(r) : "f"(x));
    return r;
}

__global__ __launch_bounds__(BT, 1)
void dtw_fused(const float* __restrict__ preds, const float* __restrict__ targs,
               const float* __restrict__ subcoef, float* __restrict__ out)
{
    const int b    = blockIdx.x;
    const int tid  = threadIdx.x;
    const int lane = tid & 31;
    const int warp = tid >> 5;
    const int sig  = lane + WSKEW * warp;     // thread skew
    const int wlo  = WSKEW * warp;            // warp-uniform active window
    const int whi  = wlo + 31 + NG;           // [wlo, whi)
    const bool l0  = (lane == 0);

    __shared__ float2 txy[MM];                // 8 KB target basis
    // Handoff slots, boundary-padded: consumer (warp w) reads slot w of the
    // opposite parity; slot 0 is a constant boundary {INF,INF} / {0,0}
    // (never written); producer warp w (<7) writes slot w+1 of current parity.
    // Layout: {bot0, bot1, Ab0, Ab1} split as D-pair + A-pair float4s.
    __shared__ float4 sbD[2][KS][NWARP];      // .x=bot0 .y=bot1 (.zw unused)
    __shared__ float4 sbA[2][KS][NWARP];      // .x=Ab0  .y=Ab1

    const float* pb = preds + (size_t)b * NN * 4;
    const float* tb = targs + (size_t)b * MM * 4;
    const float INF = __int_as_float(0x7f800000);
    const float c0s = subcoef[0];
    const float c1s = subcoef[1];

    // ---- init ----
    for (int idx = tid; idx < MM; idx += BT)
        txy[idx] = *(const float2*)(tb + (size_t)idx * 4);
    for (int idx = tid; idx < 2 * KS * NWARP; idx += BT) {
        ((float4*)sbD)[idx] = make_float4(INF, INF, INF, INF);
        ((float4*)sbA)[idx] = make_float4(0.0f, 0.0f, 0.0f, 0.0f);
    }

    float px[RR], py[RR], left[RR], Aleft[RR];
    #pragma unroll
    for (int q = 0; q < RR; ++q) {
        const float2 pv = *(const float2*)(pb + (size_t)(tid * RR + q) * 4);
        px[q] = pv.x; py[q] = pv.y;
        left[q]  = INF;
        Aleft[q] = 0.0f;
    }
    __syncthreads();

    // =====================================================================
    // Forward DP with loss propagation: thread owns rows 4t..4t+3; at step s
    // it processes column group g = s - sigma (columns 2g, 2g+1), carrying
    //   D[i,j] = cost(i,j) + min(D[i-1,j-1], D[i-1,j], D[i,j-1])
    //   A[i,j] = A[argmin parent] + |dx|*c0 + |dy|*c1
    // Parent select: first-min equality order [diag, up, left] = jnp.argmin.
    // Handoff: 4 shfls + BRANCHLESS lane0 merge (all lanes broadcast-load the
    // boundary-padded smem slot, SEL on lane==0) -> no BSSY/BSYNC per step.
    // Diag operands cached from previous step's nb1/na1 (identity holds
    // across the KS-gap slots). One barrier per KS steps.
    // Answer = A at (NN-1, MM-1), held by thread BT-1 after the last step.
    // =====================================================================
    float bot0 = INF, bot1 = INF;
    float Ab0  = 0.0f, Ab1 = 0.0f;
    float cnb1 = INF, cna1 = 0.0f;            // cached diag operands

    float cst0[RR], cst1[RR], lc0[RR], lc1[RR];   // pipelined cost & loss terms
    {   // prologue: terms for step 0 (clamped group; only warp 0 uses them)
        const int gc = min(max(0 - sig, 0), NG - 1);
        const float2 t0 = txy[2 * gc];
        const float2 t1 = txy[2 * gc + 1];
        #pragma unroll
        for (int q = 0; q < RR; ++q) {
            const float dx0 = px[q] - t0.x, dy0 = py[q] - t0.y;
            cst0[q] = fsqrt_approx(fmaf(dx0, dx0, dy0 * dy0));
            lc0[q]  = fmaf(fabsf(dy0), c1s, fabsf(dx0) * c0s);
            const float dx1 = px[q] - t1.x, dy1 = py[q] - t1.y;
            cst1[q] = fsqrt_approx(fmaf(dx1, dx1, dy1 * dy1));
            lc1[q]  = fmaf(fabsf(dy1), c1s, fabsf(dx1) * c0s);
        }
    }

    for (int e = 0; e < EPOCHS; ++e) {
        const int par = e & 1;
        #pragma unroll
        for (int ks = 0; ks < KS; ++ks) {
            const int s = e * KS + ks;

            // ---- branchless handoff ----
            const float4 vD = sbD[par ^ 1][ks][warp];   // broadcast (slot 0 = boundary)
            const float4 vA = sbA[par ^ 1][ks][warp];
            float nb0 = __shfl_up_sync(0xffffffffu, bot0, 1);
            float nb1 = __shfl_up_sync(0xffffffffu, bot1, 1);
            float na0 = __shfl_up_sync(0xffffffffu, Ab0, 1);
            float na1 = __shfl_up_sync(0xffffffffu, Ab1, 1);
            nb0 = l0 ? vD.x : nb0;
            nb1 = l0 ? vD.y : nb1;
            na0 = l0 ? vA.x : na0;
            na1 = l0 ? vA.y : na1;

            // ---- DP body (warp-uniformly skipped outside active window) ----
            if (s >= wlo && s < whi) {
                const int g = s - sig;
                if ((unsigned)g < (unsigned)NG) {
                    // ---- column c0 (diag from cache) ----
                    float up = nb0, dg = cnb1, Aup = na0, Adg = cna1;
                    float cur0[RR], Acur0[RR];
                    #pragma unroll
                    for (int q = 0; q < RR; ++q) {
                        const float lf  = left[q];
                        const float Alf = Aleft[q];
                        const float pm  = fminf(dg, lf);
                        float best = fminf(up, pm);
                        const bool p0 = (best == dg);
                        const bool p1 = (best == up);
                        const float Asel = p0 ? Adg : (p1 ? Aup : Alf);
                        if (q == 0) best = (best == INF) ? 0.0f : best;  // (0,0) seed
                        const float cur  = best + cst0[q];
                        const float Acur = Asel + lc0[q];
                        dg = lf;  Adg = Alf;
                        up = cur; Aup = Acur;
                        cur0[q] = cur; Acur0[q] = Acur;
                    }

                    // ---- column c0+1 ----
                    up = nb1; dg = nb0; Aup = na1; Adg = na0;
                    #pragma unroll
                    for (int q = 0; q < RR; ++q) {
                        const float lf  = cur0[q];
                        const float Alf = Acur0[q];
                        const float pm  = fminf(dg, lf);
                        const float best = fminf(up, pm);
                        const bool p0 = (best == dg);
                        const bool p1 = (best == up);
                        const float Asel = p0 ? Adg : (p1 ? Aup : Alf);
                        const float cur  = best + cst1[q];
                        const float Acur = Asel + lc1[q];
                        dg = lf;  Adg = Alf;
                        up = cur; Aup = Acur;
                        left[q] = cur; Aleft[q] = Acur;
                    }

                    bot0 = cur0[RR - 1];  Ab0 = Acur0[RR - 1];
                    bot1 = left[RR - 1];  Ab1 = Aleft[RR - 1];
                }
            }

            // producer: lane 31 of warps 0..6 posts into slot warp+1
            if (lane == 31 && warp < NWARP - 1) {
                sbD[par][ks][warp + 1] = make_float4(bot0, bot1, 0.0f, 0.0f);
                sbA[par][ks][warp + 1] = make_float4(Ab0,  Ab1,  0.0f, 0.0f);
            }

            // update diag cache AFTER use
            cnb1 = nb1; cna1 = na1;

            // ---- pipelined cost/loss for step s+1 (uniform-guarded) ----
            if (s + 1 >= wlo && s + 1 < whi) {
                const int gn = min(max(s + 1 - sig, 0), NG - 1);
                const float2 t0 = txy[2 * gn];
                const float2 t1 = txy[2 * gn + 1];
                #pragma unroll
                for (int q = 0; q < RR; ++q) {
                    const float dx0 = px[q] - t0.x, dy0 = py[q] - t0.y;
                    cst0[q] = fsqrt_approx(fmaf(dx0, dx0, dy0 * dy0));
                    lc0[q]  = fmaf(fabsf(dy0), c1s, fabsf(dx0) * c0s);
                    const float dx1 = px[q] - t1.x, dy1 = py[q] - t1.y;
                    cst1[q] = fsqrt_approx(fmaf(dx1, dx1, dy1 * dy1));
                    lc1[q]  = fmaf(fabsf(dy1), c1s, fabsf(dx1) * c0s);
                }
            }
        }
        __syncthreads();
    }

    // ---- result: thread BT-1's Ab1 is A at (NN-1, MM-1) ----
    if (tid == BT - 1) {
        g_loss[b] = Ab1;
        __threadfence();
        const int old = atomicAdd(&g_done, 1);
        if (old == BB - 1) {
            __threadfence();
            float t2 = 0.0f;
            #pragma unroll
            for (int x = 0; x < BB; ++x) t2 += g_loss[x];
            out[0] = t2;
            g_done = 0;   // self-reset for next graph replay
        }
    }
}

extern "C" void kernel_launch(void* const* d_in, const int* in_sizes, int n_in,
                              void* d_out, int out_size)
{
    const float* preds   = (const float*)d_in[0];
    const float* targs   = (const float*)d_in[1];
    const float* subcoef = (const float*)d_in[2];
    float* out = (float*)d_out;

    dtw_fused<<<BB, BT>>>(preds, targs, subcoef, out);
}